// round 14
// baseline (speedup 1.0000x reference)
#include <cuda_runtime.h>
#include <cuda_bf16.h>
#include <cstdint>

// Problem constants
#define NN 50000
#define NE 1600000
#define FEAT 1536
#define KH 768
#define HID 200
#define H2 400
#define NCLS 2

// Scratch
__device__ float g_H[(size_t)NN * H2];   // 80 MB: h = x@W1 (both branches)
__device__ float g_T[(size_t)NN * 4];    // layer-2 pre-msg per node
__device__ int   g_deg[NN];              // degree histogram
__device__ int   g_cur[NN];              // fill cursors
__device__ int   g_off[NN + 1];          // CSR row offsets (by dst)
__device__ int   g_csr_src[NE];          // src per CSR slot
__device__ float g_csr_w[NE];            // weight per CSR slot

// ---------------------------------------------------------------------------
// CSR build
// ---------------------------------------------------------------------------
__global__ void zero_counts_kernel() {
    int i = blockIdx.x * blockDim.x + threadIdx.x;
    if (i < NN) { g_deg[i] = 0; g_cur[i] = 0; }
}

__global__ void hist_kernel(const int* __restrict__ dst) {
    int e = blockIdx.x * blockDim.x + threadIdx.x;
    if (e < NE) atomicAdd(&g_deg[dst[e]], 1);
}

// Single-block exclusive scan over g_deg -> g_off
__global__ void scan_kernel() {
    __shared__ int part[1024];
    const int tid = threadIdx.x;
    const int chunk = (NN + 1023) / 1024;   // 49
    const int start = tid * chunk;
    const int stop = min(start + chunk, NN);

    int sum = 0;
    for (int i = start; i < stop; i++) sum += g_deg[i];
    part[tid] = sum;
    __syncthreads();

    for (int off = 1; off < 1024; off <<= 1) {
        int v = (tid >= off) ? part[tid - off] : 0;
        __syncthreads();
        part[tid] += v;
        __syncthreads();
    }

    int running = (tid == 0) ? 0 : part[tid - 1];
    for (int i = start; i < stop; i++) {
        g_off[i] = running;
        running += g_deg[i];
    }
    if (tid == 0) g_off[NN] = NE;
}

__global__ void fill_kernel(const int* __restrict__ src,
                            const int* __restrict__ dst,
                            const float* __restrict__ w) {
    int e = blockIdx.x * blockDim.x + threadIdx.x;
    if (e >= NE) return;
    const int d = dst[e];
    const int pos = g_off[d] + atomicAdd(&g_cur[d], 1);
    g_csr_src[pos] = src[e];
    g_csr_w[pos] = w[e];
}

// ---------------------------------------------------------------------------
// GEMM1 (tf32 tensor core, cp.async 2-stage pipeline):
//   H[n,0:200] = x[n,0:768]@W1a ; H[n,200:400] = x[n,768:]@W1b
// Out-of-range rows/cols are k0-invariant -> zero-fill both stages once.
// ---------------------------------------------------------------------------
#define GBM 128
#define GBN 64
#define GBK 16
#define ASTR 20
#define BSTR 72
#define A_ELEMS (GBM * ASTR)   // 2560 floats per stage
#define B_ELEMS (GBK * BSTR)   // 1152 floats per stage

__device__ __forceinline__ uint32_t f2tf32(float f) {
    uint32_t r;
    asm volatile("cvt.rna.tf32.f32 %0, %1;" : "=r"(r) : "f"(f));
    return r;
}

__device__ __forceinline__ void cp16(float* smem_dst, const float* gmem_src) {
    uint32_t saddr = (uint32_t)__cvta_generic_to_shared(smem_dst);
    asm volatile("cp.async.ca.shared.global [%0], [%1], 16;\n"
                 :: "r"(saddr), "l"(gmem_src));
}

__global__ void __launch_bounds__(256)
gemm1_tf32_kernel(const float* __restrict__ x,
                  const float* __restrict__ W1a,
                  const float* __restrict__ W1b) {
    __shared__ float As[2][A_ELEMS];
    __shared__ float Bs[2][B_ELEMS];

    const int t = threadIdx.x;
    const int warp = t >> 5;
    const int lane = t & 31;

    const int nt = blockIdx.x;            // 0..7
    const int branch = nt >> 2;
    const int col0 = (nt & 3) * GBN;
    const int m0 = blockIdx.y * GBM;

    const float* __restrict__ W = branch ? W1b : W1a;
    const int xoff = branch * KH;

    const int wm0 = (warp >> 1) * 32;
    const int wn0 = (warp & 1) * 32;

    // Load mappings (k0-invariant)
    const int aRow = t >> 2;              // 0..63 (two halves: +0, +64)
    const int aK4  = (t & 3) * 4;
    const int bK   = t >> 4;              // 0..15
    const int bC4  = (t & 15) * 4;        // 0..60
    const int bCol = col0 + bC4;

    const bool aValid0 = (m0 + aRow) < NN;
    const bool aValid1 = (m0 + aRow + 64) < NN;
    const bool bValid  = (bCol + 3) < HID;   // bCol multiple of 4: chunk all-in or all-out

    // Zero both stages once: invalid positions stay zero for the whole kernel.
    for (int i = t; i < A_ELEMS; i += 256) { As[0][i] = 0.f; As[1][i] = 0.f; }
    for (int i = t; i < B_ELEMS; i += 256) { Bs[0][i] = 0.f; Bs[1][i] = 0.f; }
    __syncthreads();

    const float* xrow0 = x + (size_t)(m0 + aRow) * FEAT + xoff + aK4;
    const float* xrow1 = x + (size_t)(m0 + aRow + 64) * FEAT + xoff + aK4;
    const float* wsrc  = W + (size_t)bK * HID + bCol;

    float acc[2][4][4];
#pragma unroll
    for (int i = 0; i < 2; i++)
#pragma unroll
        for (int j = 0; j < 4; j++)
#pragma unroll
            for (int r = 0; r < 4; r++) acc[i][j][r] = 0.f;

    const int lq = lane >> 2;
    const int lr = lane & 3;

    const int nIter = KH / GBK;   // 48

    // Prologue: prefetch stage 0 (k0 = 0)
    {
        if (aValid0) cp16(&As[0][aRow * ASTR + aK4], xrow0);
        if (aValid1) cp16(&As[0][(aRow + 64) * ASTR + aK4], xrow1);
        if (bValid)  cp16(&Bs[0][bK * BSTR + bC4], wsrc);
        asm volatile("cp.async.commit_group;");
    }

    for (int it = 0; it < nIter; it++) {
        const int buf = it & 1;
        if (it + 1 < nIter) {
            const int k1 = (it + 1) * GBK;
            if (aValid0) cp16(&As[buf ^ 1][aRow * ASTR + aK4], xrow0 + k1);
            if (aValid1) cp16(&As[buf ^ 1][(aRow + 64) * ASTR + aK4], xrow1 + k1);
            if (bValid)  cp16(&Bs[buf ^ 1][bK * BSTR + bC4], wsrc + (size_t)k1 * HID);
            asm volatile("cp.async.commit_group;");
            asm volatile("cp.async.wait_group 1;");
        } else {
            asm volatile("cp.async.wait_group 0;");
        }
        __syncthreads();

        const float* A = As[buf];
        const float* B = Bs[buf];
#pragma unroll
        for (int ks = 0; ks < 2; ks++) {
            const int kb = ks * 8;
            uint32_t afr[2][4];
#pragma unroll
            for (int mf = 0; mf < 2; mf++) {
                const int mr = wm0 + mf * 16 + lq;
                afr[mf][0] = f2tf32(A[(mr + 0) * ASTR + kb + lr]);
                afr[mf][1] = f2tf32(A[(mr + 8) * ASTR + kb + lr]);
                afr[mf][2] = f2tf32(A[(mr + 0) * ASTR + kb + lr + 4]);
                afr[mf][3] = f2tf32(A[(mr + 8) * ASTR + kb + lr + 4]);
            }
            uint32_t bfr[4][2];
#pragma unroll
            for (int nf = 0; nf < 4; nf++) {
                const int nc = wn0 + nf * 8 + lq;
                bfr[nf][0] = f2tf32(B[(kb + lr + 0) * BSTR + nc]);
                bfr[nf][1] = f2tf32(B[(kb + lr + 4) * BSTR + nc]);
            }
#pragma unroll
            for (int mf = 0; mf < 2; mf++)
#pragma unroll
                for (int nf = 0; nf < 4; nf++) {
                    asm volatile(
                        "mma.sync.aligned.m16n8k8.row.col.f32.tf32.tf32.f32 "
                        "{%0,%1,%2,%3}, {%4,%5,%6,%7}, {%8,%9}, {%0,%1,%2,%3};"
                        : "+f"(acc[mf][nf][0]), "+f"(acc[mf][nf][1]),
                          "+f"(acc[mf][nf][2]), "+f"(acc[mf][nf][3])
                        : "r"(afr[mf][0]), "r"(afr[mf][1]),
                          "r"(afr[mf][2]), "r"(afr[mf][3]),
                          "r"(bfr[nf][0]), "r"(bfr[nf][1]));
                }
        }
        __syncthreads();
    }

#pragma unroll
    for (int mf = 0; mf < 2; mf++) {
#pragma unroll
        for (int nf = 0; nf < 4; nf++) {
            const int r0 = m0 + wm0 + mf * 16 + lq;
            const int c0 = col0 + wn0 + nf * 8 + 2 * lr;
#pragma unroll
            for (int rr = 0; rr < 2; rr++) {
                const int row = r0 + rr * 8;
                if (row >= NN) continue;
#pragma unroll
                for (int cc = 0; cc < 2; cc++) {
                    const int c = c0 + cc;
                    if (c < HID)
                        g_H[(size_t)row * H2 + branch * HID + c] = acc[mf][nf][rr * 2 + cc];
                }
            }
        }
    }
}

// ---------------------------------------------------------------------------
// agg1: warp per dst node. Register-accumulate agg = sum_e w_e * H[src_e],
// then fused relu+bias+W2 projection -> T[n]. No AGG buffer, no atomics.
// ---------------------------------------------------------------------------
__global__ void __launch_bounds__(256)
agg1_kernel(const float* __restrict__ b1a,
            const float* __restrict__ W2a,
            const float* __restrict__ b1b,
            const float* __restrict__ W2b) {
    __shared__ float sW2a[HID * 2];
    __shared__ float sW2b[HID * 2];
    __shared__ float sB1[2 * HID];

    const int t = threadIdx.x;
    for (int i = t; i < HID * 2; i += blockDim.x) { sW2a[i] = W2a[i]; sW2b[i] = W2b[i]; }
    for (int i = t; i < HID; i += blockDim.x)     { sB1[i] = b1a[i]; sB1[HID + i] = b1b[i]; }
    __syncthreads();

    const int warp = t >> 5;
    const int lane = t & 31;
    const int n = blockIdx.x * 8 + warp;
    if (n >= NN) return;

    const int beg = g_off[n];
    const int end = g_off[n + 1];

    float4 acc[4];
#pragma unroll
    for (int m = 0; m < 4; m++) acc[m] = make_float4(0.f, 0.f, 0.f, 0.f);

    for (int e = beg; e < end; e++) {
        const int s = __ldg(&g_csr_src[e]);
        const float ww = __ldg(&g_csr_w[e]);
        const float4* hp = reinterpret_cast<const float4*>(g_H + (size_t)s * H2);
#pragma unroll
        for (int m = 0; m < 4; m++) {
            const int chunk = lane + m * 32;
            if (chunk < 100) {
                float4 h = __ldg(&hp[chunk]);
                acc[m].x += ww * h.x;
                acc[m].y += ww * h.y;
                acc[m].z += ww * h.z;
                acc[m].w += ww * h.w;
            }
        }
    }

    float z0 = 0.f, z1 = 0.f, z2 = 0.f, z3 = 0.f;
#pragma unroll
    for (int m = 0; m < 4; m++) {
        const int chunk = lane + m * 32;
        if (chunk >= 100) continue;
        const float av[4] = {acc[m].x, acc[m].y, acc[m].z, acc[m].w};
#pragma unroll
        for (int k = 0; k < 4; k++) {
            const int col = chunk * 4 + k;
            float a = av[k] + sB1[col];
            a = a > 0.f ? a : 0.f;
            if (col < HID) {
                z0 += a * sW2a[col * 2 + 0];
                z1 += a * sW2a[col * 2 + 1];
            } else {
                const int c2 = col - HID;
                z2 += a * sW2b[c2 * 2 + 0];
                z3 += a * sW2b[c2 * 2 + 1];
            }
        }
    }
#pragma unroll
    for (int off = 16; off > 0; off >>= 1) {
        z0 += __shfl_down_sync(0xFFFFFFFFu, z0, off);
        z1 += __shfl_down_sync(0xFFFFFFFFu, z1, off);
        z2 += __shfl_down_sync(0xFFFFFFFFu, z2, off);
        z3 += __shfl_down_sync(0xFFFFFFFFu, z3, off);
    }
    if (lane == 0)
        *reinterpret_cast<float4*>(&g_T[(size_t)n * 4]) = make_float4(z0, z1, z2, z3);
}

// ---------------------------------------------------------------------------
// agg2: warp per dst node. Gather T[src]*w, softmax both branches, vote.
// ---------------------------------------------------------------------------
__global__ void __launch_bounds__(256)
agg2_kernel(const float* __restrict__ b2a,
            const float* __restrict__ b2b,
            float* __restrict__ out) {
    const int t = threadIdx.x;
    const int warp = t >> 5;
    const int lane = t & 31;
    const int n = blockIdx.x * 8 + warp;
    if (n >= NN) return;

    const int beg = g_off[n];
    const int end = g_off[n + 1];

    float s0 = 0.f, s1 = 0.f, s2 = 0.f, s3 = 0.f;
    for (int e = beg + lane; e < end; e += 32) {
        const int s = __ldg(&g_csr_src[e]);
        const float ww = __ldg(&g_csr_w[e]);
        float4 tv = *reinterpret_cast<const float4*>(&g_T[(size_t)s * 4]);
        s0 += ww * tv.x;
        s1 += ww * tv.y;
        s2 += ww * tv.z;
        s3 += ww * tv.w;
    }
#pragma unroll
    for (int off = 16; off > 0; off >>= 1) {
        s0 += __shfl_down_sync(0xFFFFFFFFu, s0, off);
        s1 += __shfl_down_sync(0xFFFFFFFFu, s1, off);
        s2 += __shfl_down_sync(0xFFFFFFFFu, s2, off);
        s3 += __shfl_down_sync(0xFFFFFFFFu, s3, off);
    }
    if (lane == 0) {
        float za0 = s0 + b2a[0], za1 = s1 + b2a[1];
        float ma = fmaxf(za0, za1);
        float ea0 = expf(za0 - ma), ea1 = expf(za1 - ma);
        float sa = ea0 + ea1;
        float p10 = ea0 / sa, p11 = ea1 / sa;
        float zb0 = s2 + b2b[0], zb1 = s3 + b2b[1];
        float mb = fmaxf(zb0, zb1);
        float eb0 = expf(zb0 - mb), eb1 = expf(zb1 - mb);
        float sb = eb0 + eb1;
        float p20 = eb0 / sb, p21 = eb1 / sb;
        float v0 = fmaxf(p10, p20);
        float v1 = fmaxf(p11, p21);
        float inv = 1.f / (v0 + v1);
        out[n * 2 + 0] = v0 * inv;
        out[n * 2 + 1] = v1 * inv;
    }
}

// ---------------------------------------------------------------------------
// Launch
// ---------------------------------------------------------------------------
extern "C" void kernel_launch(void* const* d_in, const int* in_sizes, int n_in,
                              void* d_out, int out_size) {
    const float* x        = (const float*)d_in[0];
    const int*   edge_src = (const int*)d_in[1];
    const int*   edge_dst = (const int*)d_in[2];
    const float* edge_w   = (const float*)d_in[3];
    const float* W1a      = (const float*)d_in[4];
    const float* b1a      = (const float*)d_in[5];
    const float* W2a      = (const float*)d_in[6];
    const float* b2a      = (const float*)d_in[7];
    const float* W1b      = (const float*)d_in[8];
    const float* b1b      = (const float*)d_in[9];
    const float* W2b      = (const float*)d_in[10];
    const float* b2b      = (const float*)d_in[11];
    float* out = (float*)d_out;

    // CSR build
    zero_counts_kernel<<<(NN + 255) / 256, 256>>>();
    hist_kernel<<<(NE + 255) / 256, 256>>>(edge_dst);
    scan_kernel<<<1, 1024>>>();
    fill_kernel<<<(NE + 255) / 256, 256>>>(edge_src, edge_dst, edge_w);

    // GEMM1 (tf32 tensor core, cp.async pipelined)
    {
        dim3 grid(8, (NN + GBM - 1) / GBM);
        gemm1_tf32_kernel<<<grid, 256>>>(x, W1a, W1b);
    }

    // Fused aggregate + relu + projection -> T
    agg1_kernel<<<(NN + 7) / 8, 256>>>(b1a, W2a, b1b, W2b);

    // Fused aggregate2 + softmax + vote -> out
    agg2_kernel<<<(NN + 7) / 8, 256>>>(b2a, b2b, out);
}